// round 15
// baseline (speedup 1.0000x reference)
#include <cuda_runtime.h>
#include <cuda_fp16.h>
#include <math.h>
#include <stdint.h>

// ---------------------------------------------------------------------------
// DH-SFNN forward via mma.sync fp16 unscaled-split GEMMs (fp32-equivalent;
// subnormal-exact multiply proven R7/R9):
//   GEMM1: U = xh*wh + xh*wl + xl*wh      [3 products, A0-reuse order]
//   GEMM2: U = s*wh + s*wl                [2 products]
// R15 = R14 + (a) MODE0 product reorder (14 LDSM/kt vs 16, A-frag reuse),
// (b) GEMM2 4-stage pipeline (96 KB/CTA, still 2 CTAs/SM),
// (c) 16-deep scan prefetch (DRAM 73% -> ~85%).
// ---------------------------------------------------------------------------

#define B_    128
#define T_    250
#define IN_   700
#define INP_  704
#define H_    512
#define BR_   4
#define HB_   2048
#define OUT_  20
#define M_    (B_ * T_)    // 32000
#define WARM_ 11

// ---------------- scratch (static device globals) --------------------------
__device__ __half g_Xs [(size_t)2 * M_ * INP_];   // {xh, xl}; pad cols stay 0 (zero-init)
__device__ __half g_W1s[(size_t)2 * HB_ * INP_];  // {wh, wl}
__device__ __half g_W2s[(size_t)2 * HB_ * H_];    // {wh, wl}
__device__ float  g_U  [(size_t)M_ * HB_];        // drive
__device__ __half g_S1 [(size_t)M_ * H_];         // spikes L1
__device__ __half g_S2 [(size_t)M_ * H_];         // spikes L2
__device__ float  g_Z  [(size_t)M_ * OUT_];

// ---------------- PTX helpers ----------------------------------------------
__device__ __forceinline__ uint32_t smem_u32(const void* p) {
    uint32_t a;
    asm("{ .reg .u64 t; cvta.to.shared.u64 t, %1; cvt.u32.u64 %0, t; }"
        : "=r"(a) : "l"(p));
    return a;
}
__device__ __forceinline__ void ldmatrix_x4(uint32_t* r, uint32_t addr) {
    asm volatile("ldmatrix.sync.aligned.m8n8.x4.shared.b16 {%0,%1,%2,%3}, [%4];"
                 : "=r"(r[0]), "=r"(r[1]), "=r"(r[2]), "=r"(r[3]) : "r"(addr));
}
__device__ __forceinline__ void mma16816(float* c, const uint32_t* a,
                                         uint32_t b0, uint32_t b1) {
    asm volatile(
        "mma.sync.aligned.m16n8k16.row.col.f32.f16.f16.f32 "
        "{%0,%1,%2,%3}, {%4,%5,%6,%7}, {%8,%9}, {%0,%1,%2,%3};"
        : "+f"(c[0]), "+f"(c[1]), "+f"(c[2]), "+f"(c[3])
        : "r"(a[0]), "r"(a[1]), "r"(a[2]), "r"(a[3]), "r"(b0), "r"(b1));
}
__device__ __forceinline__ void cp16(uint32_t dst, const void* src) {
    asm volatile("cp.async.cg.shared.global [%0], [%1], 16;"
                 :: "r"(dst), "l"(src));
}
#define CP_COMMIT() asm volatile("cp.async.commit_group;" ::: "memory")
#define CP_WAIT(n)  asm volatile("cp.async.wait_group %0;" :: "n"(n) : "memory")

// Swizzled byte offset within a 128-row x 32-half tile (64 B rows, 4 quads).
__device__ __forceinline__ uint32_t swz(int row, int quad) {
    return (uint32_t)(row * 64 + ((quad ^ ((row >> 1) & 3)) << 4));
}

// ---------------- prep kernels ---------------------------------------------
__global__ void split_x_kernel(const float* __restrict__ x) {
    size_t g = (size_t)blockIdx.x * blockDim.x + threadIdx.x;  // M_ * 175 groups
    if (g >= (size_t)M_ * (IN_ / 4)) return;
    const int mm = (int)(g / (IN_ / 4));
    const int c  = (int)(g % (IN_ / 4)) * 4;
    const float4 v = *(const float4*)(x + (size_t)mm * IN_ + c);

    __half hx[4], lx[4];
    const float vv[4] = {v.x, v.y, v.z, v.w};
#pragma unroll
    for (int i = 0; i < 4; i++) {
        hx[i] = __float2half_rn(vv[i]);
        lx[i] = __float2half_rn(vv[i] - __half2float(hx[i]));
    }
    const size_t P   = (size_t)M_ * INP_;
    const size_t off = (size_t)mm * INP_ + c;
    *(__half2*)(g_Xs + off)         = __halves2half2(hx[0], hx[1]);
    *(__half2*)(g_Xs + off + 2)     = __halves2half2(hx[2], hx[3]);
    *(__half2*)(g_Xs + P + off)     = __halves2half2(lx[0], lx[1]);
    *(__half2*)(g_Xs + P + off + 2) = __halves2half2(lx[2], lx[3]);
}

__global__ void split_w_kernel(const float* __restrict__ W1,
                               const float* __restrict__ mask1,
                               const float* __restrict__ W2,
                               const float* __restrict__ mask2) {
    const size_t N1 = (size_t)HB_ * INP_;
    const size_t N2 = (size_t)HB_ * H_;
    size_t idx = (size_t)blockIdx.x * blockDim.x + threadIdx.x;
    if (idx < N1) {
        int r = (int)(idx / INP_), c = (int)(idx % INP_);
        float v = (c < IN_) ? W1[(size_t)r * IN_ + c] * mask1[(size_t)r * IN_ + c] : 0.0f;
        __half h = __float2half_rn(v);
        __half l = __float2half_rn(v - __half2float(h));  // subnormal fp16, exact in mma
        g_W1s[idx] = h; g_W1s[N1 + idx] = l;
    } else if (idx < N1 + N2) {
        size_t j = idx - N1;
        float v = W2[j] * mask2[j];
        __half h = __float2half_rn(v);
        __half l = __float2half_rn(v - __half2float(h));
        g_W2s[j] = h; g_W2s[N2 + j] = l;
    }
}

// ---------------------------------------------------------------------------
// fp16 mma.sync GEMM:  U[128m x 128n] = sum_p A[pa]*B[pb]^T
// CTA 128x128, 8 warps (2m x 4n), warp tile 64x32, K-chunk 32.
// Swizzled 8 KB tiles; NSTG-stage cp.async pipeline; 2 CTAs/SM.
// MODE 0 (3-stage): products (A0,B0),(A0,B1),(A1,B0) — A0 frags reused.
// MODE 1 (4-stage): products (A0,B0),(A0,B1) — A0 frags reused.
// ---------------------------------------------------------------------------
#define TBYTES 8192                      // 128 rows x 64 B

template <int MODE>
__global__ __launch_bounds__(256, 2)
void gemm_mma(const __half* __restrict__ A0, const __half* __restrict__ A1,
              const __half* __restrict__ Bw0, const __half* __restrict__ Bw1,
              float* __restrict__ U, int K)
{
    constexpr int NA   = (MODE == 0) ? 2 : 1;
    constexpr int NT   = NA + 2;
    constexpr int NSTG = (MODE == 0) ? 3 : 4;
    constexpr int STG  = NT * TBYTES;    // stage stride in bytes

    extern __shared__ char smem[];
    const uint32_t sb = smem_u32(smem);

    const int tid  = threadIdx.x;
    const int wid  = tid >> 5, lane = tid & 31;
    const int m0   = blockIdx.y * 128, n0 = blockIdx.x * 128;
    const int mw   = (wid >> 2) * 64;
    const int nw   = (wid & 3) * 32;

    const int a_row = lane & 15;
    const int a_q   = lane >> 4;          // quad parity from k-offset (0 or 8)
    const int b_n   = (lane & 7) + ((lane >> 4) << 3);
    const int b_q   = (lane >> 3) & 1;

    const __half* tp[NT];
    tp[0] = A0 + (size_t)m0 * K;
    if (MODE == 0) tp[1] = A1 + (size_t)m0 * K;
    tp[NA]     = Bw0 + (size_t)n0 * K;
    tp[NA + 1] = Bw1 + (size_t)n0 * K;

    const int lq = tid & 3;            // 16B quad in row
    const int lr = tid >> 2;           // row 0..63 (+64 on second pass)

    float acc[4][4][4];
#pragma unroll
    for (int i = 0; i < 4; i++)
#pragma unroll
        for (int j = 0; j < 4; j++)
#pragma unroll
            for (int q = 0; q < 4; q++) acc[i][j][q] = 0.0f;

    const int nchunk = K >> 5;

    // ---- prologue: fill NSTG-1 stages ----
#pragma unroll
    for (int s = 0; s < NSTG - 1; s++) {
        const int k0 = s << 5;
#pragma unroll
        for (int t = 0; t < NT; t++)
#pragma unroll
            for (int j = 0; j < 2; j++) {
                const int r = lr + j * 64;
                cp16(sb + s * STG + t * TBYTES + swz(r, lq),
                     tp[t] + (size_t)r * K + k0 + lq * 8);
            }
        CP_COMMIT();
    }

    for (int ch = 0; ch < nchunk; ch++) {
        CP_WAIT(NSTG - 2);
        __syncthreads();   // stage ch%NSTG ready; all warps past its last use

        if (ch + NSTG - 1 < nchunk) {
            const int k1 = (ch + NSTG - 1) << 5;
            const uint32_t so = ((ch + NSTG - 1) % NSTG) * STG;
#pragma unroll
            for (int t = 0; t < NT; t++)
#pragma unroll
                for (int j = 0; j < 2; j++) {
                    const int r = lr + j * 64;
                    cp16(sb + so + t * TBYTES + swz(r, lq),
                         tp[t] + (size_t)r * K + k1 + lq * 8);
                }
        }
        CP_COMMIT();

        const uint32_t cb = sb + (ch % NSTG) * STG;
#pragma unroll
        for (int kt = 0; kt < 2; kt++) {
            uint32_t afl[4][4], bf[2][4];

            // product 1: (A0, B0)
#pragma unroll
            for (int mi = 0; mi < 4; mi++)
                ldmatrix_x4(afl[mi],
                    cb + swz(mw + mi * 16 + a_row, kt * 2 + a_q));
#pragma unroll
            for (int ng = 0; ng < 2; ng++)
                ldmatrix_x4(bf[ng],
                    cb + NA * TBYTES + swz(nw + ng * 16 + b_n, kt * 2 + b_q));
#pragma unroll
            for (int mi = 0; mi < 4; mi++)
#pragma unroll
                for (int ni = 0; ni < 4; ni++)
                    mma16816(acc[mi][ni], afl[mi],
                             bf[ni >> 1][(ni & 1) * 2],
                             bf[ni >> 1][(ni & 1) * 2 + 1]);

            // product 2: (A0, B1) — A0 frags reused, only B reloads
#pragma unroll
            for (int ng = 0; ng < 2; ng++)
                ldmatrix_x4(bf[ng],
                    cb + (NA + 1) * TBYTES + swz(nw + ng * 16 + b_n, kt * 2 + b_q));
#pragma unroll
            for (int mi = 0; mi < 4; mi++)
#pragma unroll
                for (int ni = 0; ni < 4; ni++)
                    mma16816(acc[mi][ni], afl[mi],
                             bf[ni >> 1][(ni & 1) * 2],
                             bf[ni >> 1][(ni & 1) * 2 + 1]);

            if (MODE == 0) {
                // product 3: (A1, B0)
#pragma unroll
                for (int mi = 0; mi < 4; mi++)
                    ldmatrix_x4(afl[mi],
                        cb + TBYTES + swz(mw + mi * 16 + a_row, kt * 2 + a_q));
#pragma unroll
                for (int ng = 0; ng < 2; ng++)
                    ldmatrix_x4(bf[ng],
                        cb + NA * TBYTES + swz(nw + ng * 16 + b_n, kt * 2 + b_q));
#pragma unroll
                for (int mi = 0; mi < 4; mi++)
#pragma unroll
                    for (int ni = 0; ni < 4; ni++)
                        mma16816(acc[mi][ni], afl[mi],
                                 bf[ni >> 1][(ni & 1) * 2],
                                 bf[ni >> 1][(ni & 1) * 2 + 1]);
            }
        }
    }

    // Epilogue: direct global stores (float2), C frag layout m16n8.f32
    const int er = lane >> 2;
    const int ec = (lane & 3) * 2;
#pragma unroll
    for (int mi = 0; mi < 4; mi++) {
#pragma unroll
        for (int ni = 0; ni < 4; ni++) {
            const size_t row = (size_t)(m0 + mw + mi * 16 + er);
            const size_t col = (size_t)(n0 + nw + ni * 8 + ec);
            *(float2*)&U[row * HB_ + col] =
                make_float2(acc[mi][ni][0], acc[mi][ni][1]);
            *(float2*)&U[(row + 8) * HB_ + col] =
                make_float2(acc[mi][ni][2], acc[mi][ni][3]);
        }
    }
}

// ---------------------------------------------------------------------------
// LIF scan, branch-split (2 threads per (b,h)) with 16-deep prefetch.
// ---------------------------------------------------------------------------
__global__ __launch_bounds__(128)
void scan_kernel(const float* __restrict__ U, const float* __restrict__ tau_m,
                 const float* __restrict__ tau_n, const float* __restrict__ bias,
                 __half* __restrict__ S)
{
    const int idx  = blockIdx.x * blockDim.x + threadIdx.x;  // < 2*B_*H_
    const int pair = idx >> 1, half = idx & 1;
    const int b = pair >> 9, h = pair & 511;
    const int j0 = half * 2;

    float beta[2], ob[2], bb[2];
#pragma unroll
    for (int j = 0; j < 2; j++) {
        const float tn = tau_n[h * 4 + j0 + j];
        beta[j] = 1.0f / (1.0f + expf(-tn));
        ob[j]   = 1.0f - beta[j];
        bb[j]   = bias[h * 4 + j0 + j];
    }
    const float alpha = 1.0f / (1.0f + expf(-tau_m[h]));
    const float oa    = 1.0f - alpha;

    float d0 = 0.f, d1 = 0.f, m = 0.f, s = 0.f;
    const int st2 = HB_ / 2;   // float2 stride per t
    const float2* U2 = (const float2*)U + (size_t)b * T_ * st2 + h * 2 + half;
    __half* Sp = S + (size_t)b * T_ * H_ + h;

    float2 buf[16];
#pragma unroll
    for (int i = 0; i < 16; i++) buf[i] = U2[(size_t)i * st2];

    for (int t0 = 0; t0 < 256; t0 += 16) {
#pragma unroll
        for (int i = 0; i < 16; i++) {
            const int t = t0 + i;
            const float2 u = buf[i];
            const int tp = (t + 16 < T_) ? (t + 16) : (T_ - 1);
            buf[i] = U2[(size_t)tp * st2];

            d0 = beta[0] * d0 + ob[0] * (u.x + bb[0]);
            d1 = beta[1] * d1 + ob[1] * (u.y + bb[1]);

            const float p  = d0 + d1;
            const float q  = __shfl_xor_sync(0xffffffffu, p, 1);
            m = m * alpha + oa * (p + q) - s;   // VTH=1, DT=1
            s = (m > 1.0f) ? 1.0f : 0.0f;
            if (half == 0 && t < T_) Sp[(size_t)t * H_] = __float2half_rn(s);
        }
    }
}

// ---------------------------------------------------------------------------
// GEMM3: Z[M_][20] = S2[M_][512](fp16) * Wo[20][512]^T.  64 rows/block.
// ---------------------------------------------------------------------------
__global__ __launch_bounds__(256)
void gemm3_kernel(const __half* __restrict__ S2, const float* __restrict__ Wo,
                  float* __restrict__ Z) {
    __shared__ float Wos[OUT_ * H_];   // 40 KB
    const int tid = threadIdx.x;
    for (int i = tid; i < OUT_ * H_; i += 256) Wos[i] = Wo[i];
    __syncthreads();

    const int warp = tid >> 5, lane = tid & 31;

    for (int rr = 0; rr < 8; rr++) {
        const int m = blockIdx.x * 64 + warp * 8 + rr;
        const __half* row = S2 + (size_t)m * H_;
        float r[16];
#pragma unroll
        for (int i = 0; i < 16; i++) r[i] = __half2float(row[lane + 32 * i]);

        for (int o = 0; o < OUT_; o++) {
            float p = 0.0f;
#pragma unroll
            for (int i = 0; i < 16; i++) p += r[i] * Wos[o * H_ + lane + 32 * i];
#pragma unroll
            for (int off = 16; off > 0; off >>= 1)
                p += __shfl_xor_sync(0xffffffffu, p, off);
            if (lane == 0) Z[(size_t)m * OUT_ + o] = p;
        }
    }
}

// ---------------------------------------------------------------------------
// Readout: leaky integrator + max-free per-step softmax summed over t >= 11.
// ---------------------------------------------------------------------------
__global__ __launch_bounds__(32)
void readout_kernel(const float* __restrict__ Z, const float* __restrict__ bo,
                    const float* __restrict__ tau_mo, float* __restrict__ out) {
    const int b = blockIdx.x;
    const int o = threadIdx.x;
    const bool act = (o < OUT_);

    const float ao = act ? 1.0f / (1.0f + expf(-tau_mo[o])) : 0.0f;
    const float oa = 1.0f - ao;
    const float bb = act ? bo[o] : 0.0f;

    float mo = 0.0f, acc = 0.0f;
    for (int t = 0; t < T_; t++) {
        const float z = act ? Z[((size_t)b * T_ + t) * OUT_ + o] : 0.0f;
        if (act) mo = mo * ao + oa * (z + bb);

        float e = act ? expf(mo) : 0.0f;
        float se = e;
#pragma unroll
        for (int off = 16; off > 0; off >>= 1)
            se += __shfl_xor_sync(0xffffffffu, se, off);

        if (act && t >= WARM_) acc += e / se;
    }
    if (act) out[(size_t)b * OUT_ + o] = acc;
}

// ---------------------------------------------------------------------------
// Launch
// ---------------------------------------------------------------------------
extern "C" void kernel_launch(void* const* d_in, const int* in_sizes, int n_in,
                              void* d_out, int out_size) {
    const float* x     = (const float*)d_in[0];
    const float* W1    = (const float*)d_in[1];
    const float* b1    = (const float*)d_in[2];
    const float* tm1   = (const float*)d_in[3];
    const float* tn1   = (const float*)d_in[4];
    const float* mask1 = (const float*)d_in[5];
    const float* W2    = (const float*)d_in[6];
    const float* b2    = (const float*)d_in[7];
    const float* tm2   = (const float*)d_in[8];
    const float* tn2   = (const float*)d_in[9];
    const float* mask2 = (const float*)d_in[10];
    const float* Wo    = (const float*)d_in[11];
    const float* bo    = (const float*)d_in[12];
    const float* tmo   = (const float*)d_in[13];
    float* out = (float*)d_out;

    __half *pX, *pW1s, *pW2s, *pS1, *pS2;
    float *pU, *pZ;
    cudaGetSymbolAddress((void**)&pX,   g_Xs);
    cudaGetSymbolAddress((void**)&pW1s, g_W1s);
    cudaGetSymbolAddress((void**)&pW2s, g_W2s);
    cudaGetSymbolAddress((void**)&pU,   g_U);
    cudaGetSymbolAddress((void**)&pS1,  g_S1);
    cudaGetSymbolAddress((void**)&pS2,  g_S2);
    cudaGetSymbolAddress((void**)&pZ,   g_Z);

    const size_t PX  = (size_t)M_ * INP_;
    const size_t PW1 = (size_t)HB_ * INP_;
    const size_t PW2 = (size_t)HB_ * H_;

    const int SMEM0 = 3 * 4 * TBYTES;   // 98304 B (3 stages x 4 tiles)
    const int SMEM1 = 4 * 3 * TBYTES;   // 98304 B (4 stages x 3 tiles)
    cudaFuncSetAttribute(gemm_mma<0>, cudaFuncAttributeMaxDynamicSharedMemorySize, SMEM0);
    cudaFuncSetAttribute(gemm_mma<1>, cudaFuncAttributeMaxDynamicSharedMemorySize, SMEM1);

    // 1. Prep: fp16 splits {hi, lo}
    {
        const size_t ng = (size_t)M_ * (IN_ / 4);
        split_x_kernel<<<(unsigned)((ng + 255) / 256), 256>>>(x);
        const size_t nw = (size_t)HB_ * INP_ + (size_t)HB_ * H_;
        split_w_kernel<<<(unsigned)((nw + 255) / 256), 256>>>(W1, mask1, W2, mask2);
    }

    // 2. Layer 1: U = X @ Wm1^T (3 products), scan -> S1
    {
        dim3 grid(HB_ / 128, M_ / 128);
        gemm_mma<0><<<grid, 256, SMEM0>>>(pX, pX + PX, pW1s, pW1s + PW1, pU, INP_);
    }
    scan_kernel<<<(2 * B_ * H_) / 128, 128>>>(pU, tm1, tn1, b1, pS1);

    // 3. Layer 2: U = S1 @ Wm2^T (2 products), scan -> S2
    {
        dim3 grid(HB_ / 128, M_ / 128);
        gemm_mma<1><<<grid, 256, SMEM1>>>(pS1, pS1, pW2s, pW2s + PW2, pU, H_);
    }
    scan_kernel<<<(2 * B_ * H_) / 128, 128>>>(pU, tm2, tn2, b2, pS2);

    // 4. Readout
    gemm3_kernel<<<M_ / 64, 256>>>(pS2, Wo, pZ);
    readout_kernel<<<B_, 32>>>(pZ, bo, tmo, out);
}

// round 17
// speedup vs baseline: 1.4996x; 1.4996x over previous
#include <cuda_runtime.h>
#include <cuda_fp16.h>
#include <math.h>
#include <stdint.h>

// ---------------------------------------------------------------------------
// DH-SFNN forward via mma.sync fp16 unscaled-split GEMMs (fp32-equivalent;
// subnormal-exact multiply proven R7/R9):
//   GEMM1: U = xh*wh + xl*wh + xh*wl      [3 products]
//   GEMM2: U = s*wh + s*wl                [2 products]
// R17 = R16 resubmit (infra failure, no signal). R14 base (1302.6us) plus ONE
// decoupled change: fast-math readout (__expf/__fdividef) — post-spiking path
// only, cannot flip spikes, bounded by the 1e-3 output tolerance.
// ---------------------------------------------------------------------------

#define B_    128
#define T_    250
#define IN_   700
#define INP_  704
#define H_    512
#define BR_   4
#define HB_   2048
#define OUT_  20
#define M_    (B_ * T_)    // 32000
#define WARM_ 11

// ---------------- scratch (static device globals) --------------------------
__device__ __half g_Xs [(size_t)2 * M_ * INP_];   // {xh, xl}; pad cols stay 0 (zero-init)
__device__ __half g_W1s[(size_t)2 * HB_ * INP_];  // {wh, wl}
__device__ __half g_W2s[(size_t)2 * HB_ * H_];    // {wh, wl}
__device__ float  g_U  [(size_t)M_ * HB_];        // drive
__device__ __half g_S1 [(size_t)M_ * H_];         // spikes L1
__device__ __half g_S2 [(size_t)M_ * H_];         // spikes L2
__device__ float  g_Z  [(size_t)M_ * OUT_];

// ---------------- PTX helpers ----------------------------------------------
__device__ __forceinline__ uint32_t smem_u32(const void* p) {
    uint32_t a;
    asm("{ .reg .u64 t; cvta.to.shared.u64 t, %1; cvt.u32.u64 %0, t; }"
        : "=r"(a) : "l"(p));
    return a;
}
__device__ __forceinline__ void ldmatrix_x4(uint32_t* r, uint32_t addr) {
    asm volatile("ldmatrix.sync.aligned.m8n8.x4.shared.b16 {%0,%1,%2,%3}, [%4];"
                 : "=r"(r[0]), "=r"(r[1]), "=r"(r[2]), "=r"(r[3]) : "r"(addr));
}
__device__ __forceinline__ void mma16816(float* c, const uint32_t* a,
                                         uint32_t b0, uint32_t b1) {
    asm volatile(
        "mma.sync.aligned.m16n8k16.row.col.f32.f16.f16.f32 "
        "{%0,%1,%2,%3}, {%4,%5,%6,%7}, {%8,%9}, {%0,%1,%2,%3};"
        : "+f"(c[0]), "+f"(c[1]), "+f"(c[2]), "+f"(c[3])
        : "r"(a[0]), "r"(a[1]), "r"(a[2]), "r"(a[3]), "r"(b0), "r"(b1));
}
__device__ __forceinline__ void cp16(uint32_t dst, const void* src) {
    asm volatile("cp.async.cg.shared.global [%0], [%1], 16;"
                 :: "r"(dst), "l"(src));
}
#define CP_COMMIT() asm volatile("cp.async.commit_group;" ::: "memory")
#define CP_WAIT(n)  asm volatile("cp.async.wait_group %0;" :: "n"(n) : "memory")

// Swizzled byte offset within a 128-row x 32-half tile (64 B rows, 4 quads).
__device__ __forceinline__ uint32_t swz(int row, int quad) {
    return (uint32_t)(row * 64 + ((quad ^ ((row >> 1) & 3)) << 4));
}

// ---------------- prep kernels ---------------------------------------------
__global__ void split_x_kernel(const float* __restrict__ x) {
    size_t g = (size_t)blockIdx.x * blockDim.x + threadIdx.x;  // M_ * 175 groups
    if (g >= (size_t)M_ * (IN_ / 4)) return;
    const int mm = (int)(g / (IN_ / 4));
    const int c  = (int)(g % (IN_ / 4)) * 4;
    const float4 v = *(const float4*)(x + (size_t)mm * IN_ + c);

    __half hx[4], lx[4];
    const float vv[4] = {v.x, v.y, v.z, v.w};
#pragma unroll
    for (int i = 0; i < 4; i++) {
        hx[i] = __float2half_rn(vv[i]);
        lx[i] = __float2half_rn(vv[i] - __half2float(hx[i]));
    }
    const size_t P   = (size_t)M_ * INP_;
    const size_t off = (size_t)mm * INP_ + c;
    *(__half2*)(g_Xs + off)         = __halves2half2(hx[0], hx[1]);
    *(__half2*)(g_Xs + off + 2)     = __halves2half2(hx[2], hx[3]);
    *(__half2*)(g_Xs + P + off)     = __halves2half2(lx[0], lx[1]);
    *(__half2*)(g_Xs + P + off + 2) = __halves2half2(lx[2], lx[3]);
}

__global__ void split_w_kernel(const float* __restrict__ W1,
                               const float* __restrict__ mask1,
                               const float* __restrict__ W2,
                               const float* __restrict__ mask2) {
    const size_t N1 = (size_t)HB_ * INP_;
    const size_t N2 = (size_t)HB_ * H_;
    size_t idx = (size_t)blockIdx.x * blockDim.x + threadIdx.x;
    if (idx < N1) {
        int r = (int)(idx / INP_), c = (int)(idx % INP_);
        float v = (c < IN_) ? W1[(size_t)r * IN_ + c] * mask1[(size_t)r * IN_ + c] : 0.0f;
        __half h = __float2half_rn(v);
        __half l = __float2half_rn(v - __half2float(h));  // subnormal fp16, exact in mma
        g_W1s[idx] = h; g_W1s[N1 + idx] = l;
    } else if (idx < N1 + N2) {
        size_t j = idx - N1;
        float v = W2[j] * mask2[j];
        __half h = __float2half_rn(v);
        __half l = __float2half_rn(v - __half2float(h));
        g_W2s[j] = h; g_W2s[N2 + j] = l;
    }
}

// ---------------------------------------------------------------------------
// fp16 mma.sync GEMM:  U[128m x 128n] = sum_p A[pa]*B[pb]^T   (exact R14/R13)
// CTA 128x128, 8 warps (2m x 4n), warp tile 64x32, K-chunk 32.
// Swizzled 8 KB tiles; 3-stage cp.async pipeline; 2 CTAs/SM.
// MODE 0: products (A0,B0),(A1,B0) [bf reuse],(A0,B1). MODE 1: (A0,B0),(A0,B1).
// ---------------------------------------------------------------------------
#define TBYTES 8192                      // 128 rows x 64 B
#define NSTG   3

template <int MODE>
__global__ __launch_bounds__(256, 2)
void gemm_mma(const __half* __restrict__ A0, const __half* __restrict__ A1,
              const __half* __restrict__ Bw0, const __half* __restrict__ Bw1,
              float* __restrict__ U, int K)
{
    constexpr int NA  = (MODE == 0) ? 2 : 1;
    constexpr int NT  = NA + 2;
    constexpr int STG = NT * TBYTES;     // stage stride in bytes

    extern __shared__ char smem[];
    const uint32_t sb = smem_u32(smem);

    const int tid  = threadIdx.x;
    const int wid  = tid >> 5, lane = tid & 31;
    const int m0   = blockIdx.y * 128, n0 = blockIdx.x * 128;
    const int mw   = (wid >> 2) * 64;
    const int nw   = (wid & 3) * 32;

    const int a_row = lane & 15;
    const int a_q   = lane >> 4;          // quad parity from k-offset (0 or 8)
    const int b_n   = (lane & 7) + ((lane >> 4) << 3);
    const int b_q   = (lane >> 3) & 1;

    const __half* tp[NT];
    tp[0] = A0 + (size_t)m0 * K;
    if (MODE == 0) tp[1] = A1 + (size_t)m0 * K;
    tp[NA]     = Bw0 + (size_t)n0 * K;
    tp[NA + 1] = Bw1 + (size_t)n0 * K;

    const int lq = tid & 3;            // 16B quad in row
    const int lr = tid >> 2;           // row 0..63 (+64 on second pass)

    float acc[4][4][4];
#pragma unroll
    for (int i = 0; i < 4; i++)
#pragma unroll
        for (int j = 0; j < 4; j++)
#pragma unroll
            for (int q = 0; q < 4; q++) acc[i][j][q] = 0.0f;

    const int nchunk = K >> 5;

    // ---- prologue: fill NSTG-1 stages ----
#pragma unroll
    for (int s = 0; s < NSTG - 1; s++) {
        const int k0 = s << 5;
#pragma unroll
        for (int t = 0; t < NT; t++)
#pragma unroll
            for (int j = 0; j < 2; j++) {
                const int r = lr + j * 64;
                cp16(sb + s * STG + t * TBYTES + swz(r, lq),
                     tp[t] + (size_t)r * K + k0 + lq * 8);
            }
        CP_COMMIT();
    }

    for (int ch = 0; ch < nchunk; ch++) {
        CP_WAIT(NSTG - 2);
        __syncthreads();   // stage ch%NSTG ready; all warps past its last use

        if (ch + NSTG - 1 < nchunk) {
            const int k1 = (ch + NSTG - 1) << 5;
            const uint32_t so = ((ch + NSTG - 1) % NSTG) * STG;
#pragma unroll
            for (int t = 0; t < NT; t++)
#pragma unroll
                for (int j = 0; j < 2; j++) {
                    const int r = lr + j * 64;
                    cp16(sb + so + t * TBYTES + swz(r, lq),
                         tp[t] + (size_t)r * K + k1 + lq * 8);
                }
        }
        CP_COMMIT();

        const uint32_t cb = sb + (ch % NSTG) * STG;
#pragma unroll
        for (int kt = 0; kt < 2; kt++) {
            uint32_t afl[4][4], bf[2][4];

            // product 1: (A0, B0)
#pragma unroll
            for (int mi = 0; mi < 4; mi++)
                ldmatrix_x4(afl[mi],
                    cb + swz(mw + mi * 16 + a_row, kt * 2 + a_q));
#pragma unroll
            for (int ng = 0; ng < 2; ng++)
                ldmatrix_x4(bf[ng],
                    cb + NA * TBYTES + swz(nw + ng * 16 + b_n, kt * 2 + b_q));
#pragma unroll
            for (int mi = 0; mi < 4; mi++)
#pragma unroll
                for (int ni = 0; ni < 4; ni++)
                    mma16816(acc[mi][ni], afl[mi],
                             bf[ni >> 1][(ni & 1) * 2],
                             bf[ni >> 1][(ni & 1) * 2 + 1]);

            if (MODE == 0) {
                // product 2: (A1, B0) — reuse bf
#pragma unroll
                for (int mi = 0; mi < 4; mi++)
                    ldmatrix_x4(afl[mi],
                        cb + TBYTES + swz(mw + mi * 16 + a_row, kt * 2 + a_q));
#pragma unroll
                for (int mi = 0; mi < 4; mi++)
#pragma unroll
                    for (int ni = 0; ni < 4; ni++)
                        mma16816(acc[mi][ni], afl[mi],
                                 bf[ni >> 1][(ni & 1) * 2],
                                 bf[ni >> 1][(ni & 1) * 2 + 1]);
                // product 3: (A0, B1) — reload A0
#pragma unroll
                for (int mi = 0; mi < 4; mi++)
                    ldmatrix_x4(afl[mi],
                        cb + swz(mw + mi * 16 + a_row, kt * 2 + a_q));
            }
            // final product: (*, B1)  (MODE1 reuses afl from product 1)
#pragma unroll
            for (int ng = 0; ng < 2; ng++)
                ldmatrix_x4(bf[ng],
                    cb + (NA + 1) * TBYTES + swz(nw + ng * 16 + b_n, kt * 2 + b_q));
#pragma unroll
            for (int mi = 0; mi < 4; mi++)
#pragma unroll
                for (int ni = 0; ni < 4; ni++)
                    mma16816(acc[mi][ni], afl[mi],
                             bf[ni >> 1][(ni & 1) * 2],
                             bf[ni >> 1][(ni & 1) * 2 + 1]);
        }
    }

    // Epilogue: direct global stores (float2), C frag layout m16n8.f32
    const int er = lane >> 2;
    const int ec = (lane & 3) * 2;
#pragma unroll
    for (int mi = 0; mi < 4; mi++) {
#pragma unroll
        for (int ni = 0; ni < 4; ni++) {
            const size_t row = (size_t)(m0 + mw + mi * 16 + er);
            const size_t col = (size_t)(n0 + nw + ni * 8 + ec);
            *(float2*)&U[row * HB_ + col] =
                make_float2(acc[mi][ni][0], acc[mi][ni][1]);
            *(float2*)&U[(row + 8) * HB_ + col] =
                make_float2(acc[mi][ni][2], acc[mi][ni][3]);
        }
    }
}

// ---------------------------------------------------------------------------
// LIF scan, branch-split (2 threads per (b,h)), 8-deep prefetch (exact R14).
// ---------------------------------------------------------------------------
__global__ __launch_bounds__(128)
void scan_kernel(const float* __restrict__ U, const float* __restrict__ tau_m,
                 const float* __restrict__ tau_n, const float* __restrict__ bias,
                 __half* __restrict__ S)
{
    const int idx  = blockIdx.x * blockDim.x + threadIdx.x;  // < 2*B_*H_
    const int pair = idx >> 1, half = idx & 1;
    const int b = pair >> 9, h = pair & 511;
    const int j0 = half * 2;

    float beta[2], ob[2], bb[2];
#pragma unroll
    for (int j = 0; j < 2; j++) {
        const float tn = tau_n[h * 4 + j0 + j];
        beta[j] = 1.0f / (1.0f + expf(-tn));
        ob[j]   = 1.0f - beta[j];
        bb[j]   = bias[h * 4 + j0 + j];
    }
    const float alpha = 1.0f / (1.0f + expf(-tau_m[h]));
    const float oa    = 1.0f - alpha;

    float d0 = 0.f, d1 = 0.f, m = 0.f, s = 0.f;
    const int st2 = HB_ / 2;   // float2 stride per t
    const float2* U2 = (const float2*)U + (size_t)b * T_ * st2 + h * 2 + half;
    __half* Sp = S + (size_t)b * T_ * H_ + h;

    float2 buf[8];
#pragma unroll
    for (int i = 0; i < 8; i++) buf[i] = U2[(size_t)i * st2];

    for (int t0 = 0; t0 < 256; t0 += 8) {
#pragma unroll
        for (int i = 0; i < 8; i++) {
            const int t = t0 + i;
            const float2 u = buf[i];
            const int tp = (t + 8 < T_) ? (t + 8) : (T_ - 1);
            buf[i] = U2[(size_t)tp * st2];

            d0 = beta[0] * d0 + ob[0] * (u.x + bb[0]);
            d1 = beta[1] * d1 + ob[1] * (u.y + bb[1]);

            const float p  = d0 + d1;
            const float q  = __shfl_xor_sync(0xffffffffu, p, 1);
            m = m * alpha + oa * (p + q) - s;   // VTH=1, DT=1
            s = (m > 1.0f) ? 1.0f : 0.0f;
            if (half == 0 && t < T_) Sp[(size_t)t * H_] = __float2half_rn(s);
        }
    }
}

// ---------------------------------------------------------------------------
// GEMM3: Z[M_][20] = S2[M_][512](fp16) * Wo[20][512]^T.  64 rows/block.
// ---------------------------------------------------------------------------
__global__ __launch_bounds__(256)
void gemm3_kernel(const __half* __restrict__ S2, const float* __restrict__ Wo,
                  float* __restrict__ Z) {
    __shared__ float Wos[OUT_ * H_];   // 40 KB
    const int tid = threadIdx.x;
    for (int i = tid; i < OUT_ * H_; i += 256) Wos[i] = Wo[i];
    __syncthreads();

    const int warp = tid >> 5, lane = tid & 31;

    for (int rr = 0; rr < 8; rr++) {
        const int m = blockIdx.x * 64 + warp * 8 + rr;
        const __half* row = S2 + (size_t)m * H_;
        float r[16];
#pragma unroll
        for (int i = 0; i < 16; i++) r[i] = __half2float(row[lane + 32 * i]);

        for (int o = 0; o < OUT_; o++) {
            float p = 0.0f;
#pragma unroll
            for (int i = 0; i < 16; i++) p += r[i] * Wos[o * H_ + lane + 32 * i];
#pragma unroll
            for (int off = 16; off > 0; off >>= 1)
                p += __shfl_xor_sync(0xffffffffu, p, off);
            if (lane == 0) Z[(size_t)m * OUT_ + o] = p;
        }
    }
}

// ---------------------------------------------------------------------------
// Readout: leaky integrator + max-free per-step softmax summed over t >= 11.
// POST-SPIKING path: fast-math exp/div cannot flip spikes; error (~1e-6 rel)
// lands on the final output only, 1000x under the 1e-3 tolerance.
// ---------------------------------------------------------------------------
__global__ __launch_bounds__(32)
void readout_kernel(const float* __restrict__ Z, const float* __restrict__ bo,
                    const float* __restrict__ tau_mo, float* __restrict__ out) {
    const int b = blockIdx.x;
    const int o = threadIdx.x;
    const bool act = (o < OUT_);

    const float ao = act ? 1.0f / (1.0f + expf(-tau_mo[o])) : 0.0f;
    const float oa = 1.0f - ao;
    const float bb = act ? bo[o] : 0.0f;

    float mo = 0.0f, acc = 0.0f;
    for (int t = 0; t < T_; t++) {
        const float z = act ? Z[((size_t)b * T_ + t) * OUT_ + o] : 0.0f;
        if (act) mo = mo * ao + oa * (z + bb);

        float e = act ? __expf(mo) : 0.0f;   // |mo| <= ~22, no overflow
        float se = e;
#pragma unroll
        for (int off = 16; off > 0; off >>= 1)
            se += __shfl_xor_sync(0xffffffffu, se, off);

        if (act && t >= WARM_) acc += __fdividef(e, se);
    }
    if (act) out[(size_t)b * OUT_ + o] = acc;
}

// ---------------------------------------------------------------------------
// Launch
// ---------------------------------------------------------------------------
extern "C" void kernel_launch(void* const* d_in, const int* in_sizes, int n_in,
                              void* d_out, int out_size) {
    const float* x     = (const float*)d_in[0];
    const float* W1    = (const float*)d_in[1];
    const float* b1    = (const float*)d_in[2];
    const float* tm1   = (const float*)d_in[3];
    const float* tn1   = (const float*)d_in[4];
    const float* mask1 = (const float*)d_in[5];
    const float* W2    = (const float*)d_in[6];
    const float* b2    = (const float*)d_in[7];
    const float* tm2   = (const float*)d_in[8];
    const float* tn2   = (const float*)d_in[9];
    const float* mask2 = (const float*)d_in[10];
    const float* Wo    = (const float*)d_in[11];
    const float* bo    = (const float*)d_in[12];
    const float* tmo   = (const float*)d_in[13];
    float* out = (float*)d_out;

    __half *pX, *pW1s, *pW2s, *pS1, *pS2;
    float *pU, *pZ;
    cudaGetSymbolAddress((void**)&pX,   g_Xs);
    cudaGetSymbolAddress((void**)&pW1s, g_W1s);
    cudaGetSymbolAddress((void**)&pW2s, g_W2s);
    cudaGetSymbolAddress((void**)&pU,   g_U);
    cudaGetSymbolAddress((void**)&pS1,  g_S1);
    cudaGetSymbolAddress((void**)&pS2,  g_S2);
    cudaGetSymbolAddress((void**)&pZ,   g_Z);

    const size_t PX  = (size_t)M_ * INP_;
    const size_t PW1 = (size_t)HB_ * INP_;
    const size_t PW2 = (size_t)HB_ * H_;

    const int SMEM0 = NSTG * 4 * TBYTES;   // 98304 B (3 stages x 4 tiles)
    const int SMEM1 = NSTG * 3 * TBYTES;   // 73728 B (3 stages x 3 tiles)
    cudaFuncSetAttribute(gemm_mma<0>, cudaFuncAttributeMaxDynamicSharedMemorySize, SMEM0);
    cudaFuncSetAttribute(gemm_mma<1>, cudaFuncAttributeMaxDynamicSharedMemorySize, SMEM1);

    // 1. Prep: fp16 splits {hi, lo}
    {
        const size_t ng = (size_t)M_ * (IN_ / 4);
        split_x_kernel<<<(unsigned)((ng + 255) / 256), 256>>>(x);
        const size_t nw = (size_t)HB_ * INP_ + (size_t)HB_ * H_;
        split_w_kernel<<<(unsigned)((nw + 255) / 256), 256>>>(W1, mask1, W2, mask2);
    }

    // 2. Layer 1: U = X @ Wm1^T (3 products), scan -> S1
    {
        dim3 grid(HB_ / 128, M_ / 128);
        gemm_mma<0><<<grid, 256, SMEM0>>>(pX, pX + PX, pW1s, pW1s + PW1, pU, INP_);
    }
    scan_kernel<<<(2 * B_ * H_) / 128, 128>>>(pU, tm1, tn1, b1, pS1);

    // 3. Layer 2: U = S1 @ Wm2^T (2 products), scan -> S2
    {
        dim3 grid(HB_ / 128, M_ / 128);
        gemm_mma<1><<<grid, 256, SMEM1>>>(pS1, pS1, pW2s, pW2s + PW2, pU, H_);
    }
    scan_kernel<<<(2 * B_ * H_) / 128, 128>>>(pU, tm2, tn2, b2, pS2);

    // 4. Readout
    gemm3_kernel<<<M_ / 64, 256>>>(pS2, Wo, pZ);
    readout_kernel<<<B_, 32>>>(pZ, bo, tmo, out);
}